// round 2
// baseline (speedup 1.0000x reference)
#include <cuda_runtime.h>
#include <math.h>

// Problem constants
constexpr int Lc    = 50;
constexpr int NSEQ  = 32 * 40;     // 1280 sequences
constexpr int NR    = NSEQ * Lc;   // 64000 (seq,time) rows
constexpr int H     = 128;
constexpr int G4    = 512;         // 4*H gates

// ---------------------------------------------------------------------------
// Device scratch (static globals: allocation-free per harness rules)
// ---------------------------------------------------------------------------
__device__ float g_X0[(size_t)NR * 64];         // input projection out
__device__ float g_Xa[(size_t)NR * 256];        // layer activations ping
__device__ float g_Xb[(size_t)NR * 256];        // layer activations pong
__device__ float g_xg[2][(size_t)NR * G4];      // per-direction gate preactivations
__device__ float g_h[2][NSEQ * H];              // recurrent hidden state
__device__ float g_c[2][NSEQ * H];              // recurrent cell state
__device__ float g_agg[(size_t)NSEQ * 768];     // [mean|max|final]
__device__ float g_t1[(size_t)NSEQ * 512];      // head hidden pre-LN
__device__ float g_t2[(size_t)NSEQ * 512];      // head hidden post-LN

// ---------------------------------------------------------------------------
// Kernel 1: input projection  X0 = relu([imu, t, rate] @ W_in + b_in)
// One thread per (row, out-feature). rows = n*L + l. t = l/49, rate = 1.0
// ---------------------------------------------------------------------------
__global__ __launch_bounds__(256) void inproj_kernel(
    const float* __restrict__ imu, const float* __restrict__ Win,
    const float* __restrict__ bin)
{
    int idx = blockIdx.x * 256 + threadIdx.x;   // NR*64 threads total
    int row = idx >> 6;
    int jj  = idx & 63;
    int l   = row % Lc;
    const float* xr = imu + (size_t)row * 6;
    float t    = (float)l * (1.0f / 49.0f);
    float rate = 50.0f / 50.0f;
    float acc = bin[jj];
#pragma unroll
    for (int k = 0; k < 6; k++) acc = fmaf(xr[k], Win[k * 64 + jj], acc);
    acc = fmaf(t,    Win[6 * 64 + jj], acc);
    acc = fmaf(rate, Win[7 * 64 + jj], acc);
    g_X0[(size_t)row * 64 + jj] = fmaxf(acc, 0.0f);
}

// ---------------------------------------------------------------------------
// Kernel 2: generic SGEMM with bias.  C[M,N] = A[M,K] @ B[K,N] + b1 (+ b2)
// 128x128 tile, BK=8, 8x8 per thread, 256 threads. blockIdx.z = direction
// (offsets B, C, biases). All dims are multiples of tile sizes here.
// ---------------------------------------------------------------------------
__global__ __launch_bounds__(256) void sgemm_bias(
    const float* __restrict__ A, const float* __restrict__ B,
    float* __restrict__ C,
    const float* __restrict__ bias1, const float* __restrict__ bias2,
    int M, int N, int K,
    long long sB, long long sC, long long sBias)
{
    constexpr int BM = 128, BN = 128, BK = 8, TM = 8, TN = 8;
    __shared__ float As[BK][BM];
    __shared__ float Bs[BK][BN];

    const int dir = blockIdx.z;
    B += (size_t)dir * sB;
    C += (size_t)dir * sC;
    const float* b1 = bias1 + (size_t)dir * sBias;
    const float* b2 = bias2 ? bias2 + (size_t)dir * sBias : nullptr;
    const bool hasB2 = (b2 != nullptr);

    const int cRow = blockIdx.y, cCol = blockIdx.x;
    const int tid  = threadIdx.x;
    const int tCol = tid % (BN / TN);   // 0..15
    const int tRow = tid / (BN / TN);   // 0..15

    const int aRow = tid >> 1;          // 0..127
    const int aCol = (tid & 1) * 4;     // 0 or 4
    const int bRow = tid >> 5;          // 0..7
    const int bCol = (tid & 31) * 4;    // 0..124

    const float* Ab = A + (size_t)cRow * BM * K;
    const float* Bb = B + cCol * BN;

    float acc[TM][TN] = {};
    float regM[TM], regN[TN];

    for (int k0 = 0; k0 < K; k0 += BK) {
        float4 av = *(const float4*)(Ab + (size_t)aRow * K + k0 + aCol);
        As[aCol + 0][aRow] = av.x;
        As[aCol + 1][aRow] = av.y;
        As[aCol + 2][aRow] = av.z;
        As[aCol + 3][aRow] = av.w;
        *(float4*)&Bs[bRow][bCol] =
            *(const float4*)(Bb + (size_t)(k0 + bRow) * N + bCol);
        __syncthreads();
#pragma unroll
        for (int k = 0; k < BK; k++) {
            *(float4*)&regM[0] = *(const float4*)&As[k][tRow * TM];
            *(float4*)&regM[4] = *(const float4*)&As[k][tRow * TM + 4];
            *(float4*)&regN[0] = *(const float4*)&Bs[k][tCol * TN];
            *(float4*)&regN[4] = *(const float4*)&Bs[k][tCol * TN + 4];
#pragma unroll
            for (int i = 0; i < TM; i++)
#pragma unroll
                for (int j = 0; j < TN; j++)
                    acc[i][j] = fmaf(regM[i], regN[j], acc[i][j]);
        }
        __syncthreads();
    }

#pragma unroll
    for (int i = 0; i < TM; i++) {
        size_t row = (size_t)cRow * BM + tRow * TM + i;
        float* Cr = C + row * N + cCol * BN + tCol * TN;
        const int colb = cCol * BN + tCol * TN;
#pragma unroll
        for (int j = 0; j < TN; j++) {
            float v = acc[i][j] + b1[colb + j];
            if (hasB2) v += b2[colb + j];
            Cr[j] = v;
        }
    }
}

// ---------------------------------------------------------------------------
// Kernel 3: one bidirectional LSTM step (both dirs via blockIdx.y).
// Block: 256 threads = 128 gate-cols x 2 row-halves; 20 rows per block
// -> grid (64, 2) = 128 blocks = one balanced wave on 148 SMs.
// g = xg[:,tin,:] + h_prev @ Whh ; gates ; c,h update ; write h into Xout.
// ---------------------------------------------------------------------------
__global__ __launch_bounds__(256) void lstm_step(
    const float* __restrict__ Whh,   // [2][128*512] (dir-offset applied here)
    float* __restrict__ Xout,        // [NR*256]
    int step)
{
    const int dir  = blockIdx.y;
    const int row0 = blockIdx.x * 20;
    const int tid  = threadIdx.x;
    const int j    = tid & 127;
    const int s    = tid >> 7;              // 0/1: rows s*10..s*10+9
    const int tin  = dir ? (Lc - 1 - step) : step;
    const float* W   = Whh + dir * (H * G4);
    const float* xgd = g_xg[dir];
    float* hd = g_h[dir];
    float* cd = g_c[dir];

    __shared__ float hs[20][H];
    if (step > 0) {
        for (int idx = tid; idx < 20 * H; idx += 256)
            hs[idx >> 7][idx & 127] = hd[(row0 + (idx >> 7)) * H + (idx & 127)];
    }
    __syncthreads();

    float a0[10], a1[10], a2[10], a3[10];
#pragma unroll
    for (int r = 0; r < 10; r++) {
        int row = row0 + s * 10 + r;
        const float* xr = xgd + ((size_t)row * Lc + tin) * G4 + j;
        a0[r] = xr[0]; a1[r] = xr[128]; a2[r] = xr[256]; a3[r] = xr[384];
    }

    if (step > 0) {
        const int rbase = s * 10;
#pragma unroll 4
        for (int k = 0; k < H; k++) {
            const float* wk = W + k * G4 + j;
            float w0 = wk[0], w1 = wk[128], w2 = wk[256], w3 = wk[384];
#pragma unroll
            for (int r = 0; r < 10; r++) {
                float hv = hs[rbase + r][k];
                a0[r] = fmaf(hv, w0, a0[r]);
                a1[r] = fmaf(hv, w1, a1[r]);
                a2[r] = fmaf(hv, w2, a2[r]);
                a3[r] = fmaf(hv, w3, a3[r]);
            }
        }
    }

#pragma unroll
    for (int r = 0; r < 10; r++) {
        int row = row0 + s * 10 + r;
        float cold = (step > 0) ? cd[row * H + j] : 0.0f;
        float ig = 1.0f / (1.0f + expf(-a0[r]));
        float fg = 1.0f / (1.0f + expf(-a1[r]));
        float gg = tanhf(a2[r]);
        float og = 1.0f / (1.0f + expf(-a3[r]));
        float cn = fmaf(fg, cold, ig * gg);
        float hn = og * tanhf(cn);
        cd[row * H + j] = cn;
        hd[row * H + j] = hn;
        Xout[((size_t)row * Lc + tin) * 256 + dir * H + j] = hn;
    }
}

// ---------------------------------------------------------------------------
// Kernel 4: aggregation  agg = [mean_L | max_L | (fwd@L-1, bwd@0)]  [NSEQ,768]
// ---------------------------------------------------------------------------
__global__ __launch_bounds__(256) void agg_kernel(const float* __restrict__ X)
{
    int n = blockIdx.x, f = threadIdx.x;
    const float* base = X + (size_t)n * Lc * 256 + f;
    float s = 0.0f, m = -1e30f;
#pragma unroll 5
    for (int l = 0; l < Lc; l++) {
        float v = base[(size_t)l * 256];
        s += v; m = fmaxf(m, v);
    }
    g_agg[(size_t)n * 768 + f]       = s * (1.0f / Lc);
    g_agg[(size_t)n * 768 + 256 + f] = m;
    g_agg[(size_t)n * 768 + 512 + f] = (f < H) ? base[(Lc - 1) * 256] : base[0];
}

// ---------------------------------------------------------------------------
// Kernel 5: LayerNorm(512) + ReLU, block per row
// ---------------------------------------------------------------------------
__global__ __launch_bounds__(256) void ln_relu(
    const float* __restrict__ x, float* __restrict__ y,
    const float* __restrict__ gam, const float* __restrict__ bet)
{
    int row = blockIdx.x, tid = threadIdx.x;
    const float* xr = x + (size_t)row * 512;
    float v0 = xr[tid], v1 = xr[tid + 256];
    float s = v0 + v1, q = v0 * v0 + v1 * v1;
    __shared__ float ss[8], sq[8];
#pragma unroll
    for (int o = 16; o > 0; o >>= 1) {
        s += __shfl_down_sync(~0u, s, o);
        q += __shfl_down_sync(~0u, q, o);
    }
    int w = tid >> 5;
    if ((tid & 31) == 0) { ss[w] = s; sq[w] = q; }
    __syncthreads();
    if (tid == 0) {
        float S = 0.0f, Q = 0.0f;
        for (int i = 0; i < 8; i++) { S += ss[i]; Q += sq[i]; }
        ss[0] = S; sq[0] = Q;
    }
    __syncthreads();
    float mu  = ss[0] * (1.0f / 512.0f);
    float var = sq[0] * (1.0f / 512.0f) - mu * mu;
    float rs  = rsqrtf(var + 1e-5f);
    y[(size_t)row * 512 + tid]       = fmaxf((v0 - mu) * rs * gam[tid]       + bet[tid],       0.0f);
    y[(size_t)row * 512 + tid + 256] = fmaxf((v1 - mu) * rs * gam[tid + 256] + bet[tid + 256], 0.0f);
}

// ---------------------------------------------------------------------------
// Host orchestration (graph-capturable: kernel launches only)
// ---------------------------------------------------------------------------
extern "C" void kernel_launch(void* const* d_in, const int* in_sizes, int n_in,
                              void* d_out, int out_size)
{
    const float* imu   = (const float*)d_in[0];
    const float* W_in  = (const float*)d_in[1];
    const float* b_in  = (const float*)d_in[2];
    const float* Wih[3] = {(const float*)d_in[3],  (const float*)d_in[7],  (const float*)d_in[11]};
    const float* Whh[3] = {(const float*)d_in[4],  (const float*)d_in[8],  (const float*)d_in[12]};
    const float* bih[3] = {(const float*)d_in[5],  (const float*)d_in[9],  (const float*)d_in[13]};
    const float* bhh[3] = {(const float*)d_in[6],  (const float*)d_in[10], (const float*)d_in[14]};
    const float* Wout1 = (const float*)d_in[15];
    const float* bout1 = (const float*)d_in[16];
    const float* ln_g  = (const float*)d_in[17];
    const float* ln_b  = (const float*)d_in[18];
    const float* Wout2 = (const float*)d_in[19];
    const float* bout2 = (const float*)d_in[20];
    float* out = (float*)d_out;

    float *pX0, *pXa, *pXb, *pxg, *pagg, *pt1, *pt2;
    cudaGetSymbolAddress((void**)&pX0,  g_X0);
    cudaGetSymbolAddress((void**)&pXa,  g_Xa);
    cudaGetSymbolAddress((void**)&pXb,  g_Xb);
    cudaGetSymbolAddress((void**)&pxg,  g_xg);
    cudaGetSymbolAddress((void**)&pagg, g_agg);
    cudaGetSymbolAddress((void**)&pt1,  g_t1);
    cudaGetSymbolAddress((void**)&pt2,  g_t2);

    // 1) input projection
    inproj_kernel<<<(NR * 64) / 256, 256>>>(imu, W_in, b_in);

    // 2) three BiLSTM layers
    float* Xin  = pX0;
    int    Kin  = 64;
    float* Xout = pXa;
    for (int layer = 0; layer < 3; layer++) {
        // gate preactivations for both directions: xg = Xin @ Wih + (bih+bhh)
        sgemm_bias<<<dim3(G4 / 128, NR / 128, 2), 256>>>(
            Xin, Wih[layer], pxg, bih[layer], bhh[layer],
            NR, G4, Kin,
            (long long)Kin * G4, (long long)NR * G4, (long long)G4);
        // 50 recurrent steps (fwd+bwd in parallel via grid.y)
        for (int s = 0; s < Lc; s++)
            lstm_step<<<dim3(NSEQ / 20, 2), 256>>>(Whh[layer], Xout, s);
        Xin = Xout;
        Kin = 256;
        Xout = (Xin == pXa) ? pXb : pXa;
    }
    float* Xfinal = Xin;  // layer-2 output (g_Xa)

    // 3) aggregation
    agg_kernel<<<NSEQ, 256>>>(Xfinal);

    // 4) head: GEMM1 -> LN+ReLU -> GEMM2
    sgemm_bias<<<dim3(512 / 128, NSEQ / 128, 1), 256>>>(
        pagg, Wout1, pt1, bout1, nullptr, NSEQ, 512, 768, 0, 0, 0);
    ln_relu<<<NSEQ, 256>>>(pt1, pt2, ln_g, ln_b);
    sgemm_bias<<<dim3(256 / 128, NSEQ / 128, 1), 256>>>(
        pt2, Wout2, out, bout2, nullptr, NSEQ, 256, 512, 0, 0, 0);
}

// round 3
// speedup vs baseline: 1.2162x; 1.2162x over previous
#include <cuda_runtime.h>
#include <math.h>

// Problem constants
constexpr int Lc    = 50;
constexpr int NSEQ  = 32 * 40;     // 1280 sequences
constexpr int NR    = NSEQ * Lc;   // 64000 (seq,time) rows
constexpr int H     = 128;
constexpr int G4    = 512;         // 4*H gates

// ---------------------------------------------------------------------------
// Device scratch
// ---------------------------------------------------------------------------
__device__ float g_X0[(size_t)NR * 64];
__device__ float g_Xa[(size_t)NR * 256];
__device__ float g_Xb[(size_t)NR * 256];
__device__ float g_xg[2][(size_t)NR * G4];
__device__ float g_hbuf[2][2][NSEQ * H];     // [step parity][dir][row*H+k]
__device__ int   g_flags[2][2][32];          // [dir][jtile][rowgroup]
__device__ float g_agg[(size_t)NSEQ * 768];
__device__ float g_t1[(size_t)NSEQ * 512];
__device__ float g_t2[(size_t)NSEQ * 512];

// ---------------------------------------------------------------------------
// f32x2 helpers (Blackwell packed fp32 — 2x FFMA throughput vs scalar)
// ---------------------------------------------------------------------------
__device__ __forceinline__ float2 ffma2(float2 a, float2 b, float2 c) {
    unsigned long long ud;
    asm("fma.rn.f32x2 %0, %1, %2, %3;"
        : "=l"(ud)
        : "l"(*(unsigned long long*)&a),
          "l"(*(unsigned long long*)&b),
          "l"(*(unsigned long long*)&c));
    float2 d; *(unsigned long long*)&d = ud; return d;
}
__device__ __forceinline__ float2 pack2(float lo, float hi) {
    float2 r; r.x = lo; r.y = hi; return r;
}

__device__ __forceinline__ float sigm_(float x) {
    return __fdividef(1.0f, 1.0f + __expf(-x));
}
__device__ __forceinline__ float tanh_(float x) {
    return __fdividef(2.0f, 1.0f + __expf(-2.0f * x)) - 1.0f;
}

// ---------------------------------------------------------------------------
// Kernel: reset pairwise-sync flags (run once per replay, before layer 0)
// ---------------------------------------------------------------------------
__global__ void reset_flags() {
    ((int*)g_flags)[threadIdx.x] = 0;
}

// ---------------------------------------------------------------------------
// Kernel 1: input projection
// ---------------------------------------------------------------------------
__global__ __launch_bounds__(256) void inproj_kernel(
    const float* __restrict__ imu, const float* __restrict__ Win,
    const float* __restrict__ bin)
{
    int idx = blockIdx.x * 256 + threadIdx.x;
    int row = idx >> 6;
    int jj  = idx & 63;
    int l   = row % Lc;
    const float* xr = imu + (size_t)row * 6;
    float t    = (float)l * (1.0f / 49.0f);
    float rate = 1.0f;
    float acc = bin[jj];
#pragma unroll
    for (int k = 0; k < 6; k++) acc = fmaf(xr[k], Win[k * 64 + jj], acc);
    acc = fmaf(t,    Win[6 * 64 + jj], acc);
    acc = fmaf(rate, Win[7 * 64 + jj], acc);
    g_X0[(size_t)row * 64 + jj] = fmaxf(acc, 0.0f);
}

// ---------------------------------------------------------------------------
// Kernel 2: SGEMM with bias, f32x2 inner product.
// 128x128 tile, BK=8, 8x8 per thread (as 8x4 float2), 256 threads.
// ---------------------------------------------------------------------------
__global__ __launch_bounds__(256) void sgemm_bias(
    const float* __restrict__ A, const float* __restrict__ B,
    float* __restrict__ C,
    const float* __restrict__ bias1, const float* __restrict__ bias2,
    int M, int N, int K,
    long long sB, long long sC, long long sBias)
{
    constexpr int BM = 128, BN = 128, BK = 8, TM = 8, TN = 8;
    __shared__ float As[BK][BM];
    __shared__ float Bs[BK][BN];

    const int dir = blockIdx.z;
    B += (size_t)dir * sB;
    C += (size_t)dir * sC;
    const float* b1 = bias1 + (size_t)dir * sBias;
    const float* b2 = bias2 ? bias2 + (size_t)dir * sBias : nullptr;
    const bool hasB2 = (b2 != nullptr);

    const int cRow = blockIdx.y, cCol = blockIdx.x;
    const int tid  = threadIdx.x;
    const int tCol = tid % (BN / TN);
    const int tRow = tid / (BN / TN);

    const int aRow = tid >> 1;
    const int aCol = (tid & 1) * 4;
    const int bRow = tid >> 5;
    const int bCol = (tid & 31) * 4;

    const float* Ab = A + (size_t)cRow * BM * K;
    const float* Bb = B + cCol * BN;

    float2 acc2[TM][TN / 2];
#pragma unroll
    for (int i = 0; i < TM; i++)
#pragma unroll
        for (int j = 0; j < TN / 2; j++) acc2[i][j] = pack2(0.f, 0.f);

    float regM[TM];

    for (int k0 = 0; k0 < K; k0 += BK) {
        float4 av = *(const float4*)(Ab + (size_t)aRow * K + k0 + aCol);
        As[aCol + 0][aRow] = av.x;
        As[aCol + 1][aRow] = av.y;
        As[aCol + 2][aRow] = av.z;
        As[aCol + 3][aRow] = av.w;
        *(float4*)&Bs[bRow][bCol] =
            *(const float4*)(Bb + (size_t)(k0 + bRow) * N + bCol);
        __syncthreads();
#pragma unroll
        for (int k = 0; k < BK; k++) {
            *(float4*)&regM[0] = *(const float4*)&As[k][tRow * TM];
            *(float4*)&regM[4] = *(const float4*)&As[k][tRow * TM + 4];
            float4 bn0 = *(const float4*)&Bs[k][tCol * TN];
            float4 bn1 = *(const float4*)&Bs[k][tCol * TN + 4];
            float2 n0 = pack2(bn0.x, bn0.y), n1 = pack2(bn0.z, bn0.w);
            float2 n2 = pack2(bn1.x, bn1.y), n3 = pack2(bn1.z, bn1.w);
#pragma unroll
            for (int i = 0; i < TM; i++) {
                float2 m2 = pack2(regM[i], regM[i]);
                acc2[i][0] = ffma2(m2, n0, acc2[i][0]);
                acc2[i][1] = ffma2(m2, n1, acc2[i][1]);
                acc2[i][2] = ffma2(m2, n2, acc2[i][2]);
                acc2[i][3] = ffma2(m2, n3, acc2[i][3]);
            }
        }
        __syncthreads();
    }

#pragma unroll
    for (int i = 0; i < TM; i++) {
        size_t row = (size_t)cRow * BM + tRow * TM + i;
        float* Cr = C + row * N + cCol * BN + tCol * TN;
        const int colb = cCol * BN + tCol * TN;
#pragma unroll
        for (int j2 = 0; j2 < TN / 2; j2++) {
            float vx = acc2[i][j2].x + b1[colb + 2 * j2];
            float vy = acc2[i][j2].y + b1[colb + 2 * j2 + 1];
            if (hasB2) { vx += b2[colb + 2 * j2]; vy += b2[colb + 2 * j2 + 1]; }
            Cr[2 * j2]     = vx;
            Cr[2 * j2 + 1] = vy;
        }
    }
}

// ---------------------------------------------------------------------------
// Kernel 3: PERSISTENT BiLSTM layer — all 50 steps in one launch.
// 128 blocks (co-resident, 148 SMs): dir(2) x jtile(2) x rowgroup(32).
// Block: 40 rows x 64 hidden units. Whh slice (128KB) staged in smem.
// c lives in registers. h exchanged with the j-tile partner block via
// parity-double-buffered global memory + pairwise flag spin.
// Thread map: jj = tid&63 (hidden unit), rg = tid>>6 (10 rows each).
// Inner product uses f32x2 on row pairs.
// ---------------------------------------------------------------------------
__global__ __launch_bounds__(256) void lstm_layer(
    const float* __restrict__ Whh,    // [2][128*512]
    const float* __restrict__ xgb,    // g_xg base: [2][NR*512]
    float* __restrict__ Xout,         // [NR*256]
    int layer)
{
    extern __shared__ float smem[];
    float4* ws  = (float4*)smem;                       // [128][64] gate quad per (k,jj)
    float2* hs2 = (float2*)(smem + 128 * 64 * 4);      // [rg=4][p=5][k=128] row-pairs

    const int b    = blockIdx.x;
    const int dir  = b >> 6;
    const int jt   = (b >> 5) & 1;
    const int rgI  = b & 31;
    const int row0 = rgI * 40;
    const int tid  = threadIdx.x;
    const int jj   = tid & 63;
    const int rg   = tid >> 6;
    const int base = layer * Lc;

    const float* W   = Whh + (size_t)dir * (H * G4);
    const float* xgd = xgb + (size_t)dir * NR * G4;
    volatile int* myflag = &g_flags[dir][jt][rgI];
    volatile int* pflag  = &g_flags[dir][jt ^ 1][rgI];

    // Stage Whh slice: ws[k][jj] = {W[k][jt*64+jj + g*128]}_{g=0..3}
    for (int idx = tid; idx < 128 * 64; idx += 256) {
        int k = idx >> 6, j = idx & 63;
        int col = jt * 64 + j;
        const float* wk = W + (size_t)k * G4 + col;
        ws[idx] = make_float4(wk[0], wk[128], wk[256], wk[384]);
    }
    __syncthreads();

    float c[10];
#pragma unroll
    for (int r = 0; r < 10; r++) c[r] = 0.0f;

    for (int step = 0; step < Lc; step++) {
        const int tin = dir ? (Lc - 1 - step) : step;

        // accumulators initialized from xg (prefetch before sync)
        float2 acc[4][5];
#pragma unroll
        for (int p = 0; p < 5; p++) {
            int rowA = row0 + rg * 10 + 2 * p;
            const float* xa = xgd + ((size_t)rowA * Lc + tin) * G4 + jt * 64 + jj;
            const float* xb = xa + (size_t)Lc * G4;   // rowA+1
#pragma unroll
            for (int g = 0; g < 4; g++)
                acc[g][p] = pack2(xa[g * 128], xb[g * 128]);
        }

        if (step > 0) {
            // wait for partner's h of step-1
            const int want = base + step;
            if (tid == 0) {
                while (*pflag < want) __nanosleep(64);
            }
            __syncthreads();
            __threadfence();

            // stage h (both halves) for our 40 rows, as row pairs
            const float* hb = g_hbuf[(step + 1) & 1][dir];   // parity of step-1
            for (int idx = tid; idx < 40 * 128; idx += 256) {
                int rl = idx >> 7, k = idx & 127;
                float v = hb[(size_t)(row0 + rl) * H + k];
                int trg = rl / 10, within = rl % 10;
                ((float*)&hs2[((size_t)trg * 5 + (within >> 1)) * 128 + k])[within & 1] = v;
            }
            __syncthreads();

            const float2* hrow = hs2 + (size_t)rg * 5 * 128;
#pragma unroll 2
            for (int k = 0; k < 128; k++) {
                float4 w4 = ws[(size_t)k * 64 + jj];
                float2 w0 = pack2(w4.x, w4.x);
                float2 w1 = pack2(w4.y, w4.y);
                float2 w2 = pack2(w4.z, w4.z);
                float2 w3 = pack2(w4.w, w4.w);
#pragma unroll
                for (int p = 0; p < 5; p++) {
                    float2 h2 = hrow[(size_t)p * 128 + k];
                    acc[0][p] = ffma2(h2, w0, acc[0][p]);
                    acc[1][p] = ffma2(h2, w1, acc[1][p]);
                    acc[2][p] = ffma2(h2, w2, acc[2][p]);
                    acc[3][p] = ffma2(h2, w3, acc[3][p]);
                }
            }
        }

        // gates + state update
        float hval[10];
#pragma unroll
        for (int p = 0; p < 5; p++) {
#pragma unroll
            for (int hh = 0; hh < 2; hh++) {
                int r = 2 * p + hh;
                float ai = hh ? acc[0][p].y : acc[0][p].x;
                float af = hh ? acc[1][p].y : acc[1][p].x;
                float ag = hh ? acc[2][p].y : acc[2][p].x;
                float ao = hh ? acc[3][p].y : acc[3][p].x;
                float ig = sigm_(ai);
                float fg = sigm_(af);
                float gg = tanh_(ag);
                float og = sigm_(ao);
                float cn = fmaf(fg, c[r], ig * gg);
                c[r] = cn;
                hval[r] = og * tanh_(cn);
            }
        }

        // publish h (parity buffer) + layer output
        float* hbW = g_hbuf[step & 1][dir];
#pragma unroll
        for (int r = 0; r < 10; r++) {
            int row = row0 + rg * 10 + r;
            hbW[(size_t)row * H + jt * 64 + jj] = hval[r];
            Xout[((size_t)row * Lc + tin) * 256 + dir * H + jt * 64 + jj] = hval[r];
        }
        __threadfence();
        __syncthreads();
        if (tid == 0) atomicExch((int*)myflag, base + step + 1);
    }
}

// ---------------------------------------------------------------------------
// Kernel 4: aggregation
// ---------------------------------------------------------------------------
__global__ __launch_bounds__(256) void agg_kernel(const float* __restrict__ X)
{
    int n = blockIdx.x, f = threadIdx.x;
    const float* base = X + (size_t)n * Lc * 256 + f;
    float s = 0.0f, m = -1e30f;
#pragma unroll 5
    for (int l = 0; l < Lc; l++) {
        float v = base[(size_t)l * 256];
        s += v; m = fmaxf(m, v);
    }
    g_agg[(size_t)n * 768 + f]       = s * (1.0f / Lc);
    g_agg[(size_t)n * 768 + 256 + f] = m;
    g_agg[(size_t)n * 768 + 512 + f] = (f < H) ? base[(Lc - 1) * 256] : base[0];
}

// ---------------------------------------------------------------------------
// Kernel 5: LayerNorm(512) + ReLU
// ---------------------------------------------------------------------------
__global__ __launch_bounds__(256) void ln_relu(
    const float* __restrict__ x, float* __restrict__ y,
    const float* __restrict__ gam, const float* __restrict__ bet)
{
    int row = blockIdx.x, tid = threadIdx.x;
    const float* xr = x + (size_t)row * 512;
    float v0 = xr[tid], v1 = xr[tid + 256];
    float s = v0 + v1, q = v0 * v0 + v1 * v1;
    __shared__ float ss[8], sq[8];
#pragma unroll
    for (int o = 16; o > 0; o >>= 1) {
        s += __shfl_down_sync(~0u, s, o);
        q += __shfl_down_sync(~0u, q, o);
    }
    int w = tid >> 5;
    if ((tid & 31) == 0) { ss[w] = s; sq[w] = q; }
    __syncthreads();
    if (tid == 0) {
        float S = 0.0f, Q = 0.0f;
        for (int i = 0; i < 8; i++) { S += ss[i]; Q += sq[i]; }
        ss[0] = S; sq[0] = Q;
    }
    __syncthreads();
    float mu  = ss[0] * (1.0f / 512.0f);
    float var = sq[0] * (1.0f / 512.0f) - mu * mu;
    float rs  = rsqrtf(var + 1e-5f);
    y[(size_t)row * 512 + tid]       = fmaxf((v0 - mu) * rs * gam[tid]       + bet[tid],       0.0f);
    y[(size_t)row * 512 + tid + 256] = fmaxf((v1 - mu) * rs * gam[tid + 256] + bet[tid + 256], 0.0f);
}

// ---------------------------------------------------------------------------
// Host orchestration
// ---------------------------------------------------------------------------
extern "C" void kernel_launch(void* const* d_in, const int* in_sizes, int n_in,
                              void* d_out, int out_size)
{
    const float* imu   = (const float*)d_in[0];
    const float* W_in  = (const float*)d_in[1];
    const float* b_in  = (const float*)d_in[2];
    const float* Wih[3] = {(const float*)d_in[3],  (const float*)d_in[7],  (const float*)d_in[11]};
    const float* Whh[3] = {(const float*)d_in[4],  (const float*)d_in[8],  (const float*)d_in[12]};
    const float* bih[3] = {(const float*)d_in[5],  (const float*)d_in[9],  (const float*)d_in[13]};
    const float* bhh[3] = {(const float*)d_in[6],  (const float*)d_in[10], (const float*)d_in[14]};
    const float* Wout1 = (const float*)d_in[15];
    const float* bout1 = (const float*)d_in[16];
    const float* ln_g  = (const float*)d_in[17];
    const float* ln_b  = (const float*)d_in[18];
    const float* Wout2 = (const float*)d_in[19];
    const float* bout2 = (const float*)d_in[20];
    float* out = (float*)d_out;

    float *pX0, *pXa, *pXb, *pxg, *pagg, *pt1, *pt2;
    cudaGetSymbolAddress((void**)&pX0,  g_X0);
    cudaGetSymbolAddress((void**)&pXa,  g_Xa);
    cudaGetSymbolAddress((void**)&pXb,  g_Xb);
    cudaGetSymbolAddress((void**)&pxg,  g_xg);
    cudaGetSymbolAddress((void**)&pagg, g_agg);
    cudaGetSymbolAddress((void**)&pt1,  g_t1);
    cudaGetSymbolAddress((void**)&pt2,  g_t2);

    // persistent LSTM needs > 48KB dynamic smem
    constexpr int LSTM_SMEM = 128 * 64 * 16 + 4 * 5 * 128 * 8;   // 131072 + 20480
    cudaFuncSetAttribute(lstm_layer,
                         cudaFuncAttributeMaxDynamicSharedMemorySize, LSTM_SMEM);

    reset_flags<<<1, 128>>>();
    inproj_kernel<<<(NR * 64) / 256, 256>>>(imu, W_in, b_in);

    float* Xin  = pX0;
    int    Kin  = 64;
    float* Xout = pXa;
    for (int layer = 0; layer < 3; layer++) {
        sgemm_bias<<<dim3(G4 / 128, NR / 128, 2), 256>>>(
            Xin, Wih[layer], pxg, bih[layer], bhh[layer],
            NR, G4, Kin,
            (long long)Kin * G4, (long long)NR * G4, (long long)G4);
        lstm_layer<<<128, 256, LSTM_SMEM>>>(Whh[layer], pxg, Xout, layer);
        Xin = Xout;
        Kin = 256;
        Xout = (Xin == pXa) ? pXb : pXa;
    }
    float* Xfinal = Xin;

    agg_kernel<<<NSEQ, 256>>>(Xfinal);
    sgemm_bias<<<dim3(512 / 128, NSEQ / 128, 1), 256>>>(
        pagg, Wout1, pt1, bout1, nullptr, NSEQ, 512, 768, 0, 0, 0);
    ln_relu<<<NSEQ, 256>>>(pt1, pt2, ln_g, ln_b);
    sgemm_bias<<<dim3(256 / 128, NSEQ / 128, 1), 256>>>(
        pt2, Wout2, out, bout2, nullptr, NSEQ, 256, 512, 0, 0, 0);
}